// round 4
// baseline (speedup 1.0000x reference)
#include <cuda_runtime.h>
#include <cuda_bf16.h>

#define N_NODES 5
#define EMB 16
#define HID 32

// LUT[c][e] : value to write for a cell whose game_state char == c, c in 0..5.
// c == 0      -> emb_table[0][e]   (gse fallback; chars outside 1..5)
// c in 1..5   -> node_emb[c-1][e]  (GCN output rows)
__device__ float g_lut[6 * EMB];

// ---------------------------------------------------------------------------
// Kernel 1: tiny GCN on 5 nodes -> fill g_lut. One block, 192 threads.
// ---------------------------------------------------------------------------
__global__ void gcn_build_lut(const float* __restrict__ emb,   // [5,16]
                              const float* __restrict__ A,     // [5,5]
                              const float* __restrict__ W0,    // [32,16]
                              const float* __restrict__ W1,    // [32,32]
                              const float* __restrict__ W2,    // [32,32]
                              const float* __restrict__ Wf,    // [16,32]
                              const float* __restrict__ bf)    // [16]
{
    __shared__ float x0[N_NODES][EMB];   // A @ emb_table
    __shared__ float h[N_NODES][HID];
    __shared__ float y[N_NODES][HID];

    const int t = threadIdx.x;

    // x0 = A @ emb_table  [5,16]
    if (t < N_NODES * EMB) {
        int i = t / EMB, j = t % EMB;
        float s = 0.f;
        #pragma unroll
        for (int k = 0; k < N_NODES; k++) s += A[i * N_NODES + k] * emb[k * EMB + j];
        x0[i][j] = s;
    }
    __syncthreads();

    // h = relu(x0 @ W0^T)  [5,32]
    if (t < N_NODES * HID) {
        int i = t / HID, o = t % HID;
        float s = 0.f;
        #pragma unroll
        for (int j = 0; j < EMB; j++) s += x0[i][j] * W0[o * EMB + j];
        h[i][o] = fmaxf(s, 0.f);
    }
    __syncthreads();

    // round 1: y = A@h ; h = relu(y @ W1^T)
    if (t < N_NODES * HID) {
        int i = t / HID, o = t % HID;
        float s = 0.f;
        #pragma unroll
        for (int k = 0; k < N_NODES; k++) s += A[i * N_NODES + k] * h[k][o];
        y[i][o] = s;
    }
    __syncthreads();
    if (t < N_NODES * HID) {
        int i = t / HID, o = t % HID;
        float s = 0.f;
        #pragma unroll
        for (int j = 0; j < HID; j++) s += y[i][j] * W1[o * HID + j];
        h[i][o] = fmaxf(s, 0.f);
    }
    __syncthreads();

    // round 2: y = A@h ; h = relu(y @ W2^T)
    if (t < N_NODES * HID) {
        int i = t / HID, o = t % HID;
        float s = 0.f;
        #pragma unroll
        for (int k = 0; k < N_NODES; k++) s += A[i * N_NODES + k] * h[k][o];
        y[i][o] = s;
    }
    __syncthreads();
    if (t < N_NODES * HID) {
        int i = t / HID, o = t % HID;
        float s = 0.f;
        #pragma unroll
        for (int j = 0; j < HID; j++) s += y[i][j] * W2[o * HID + j];
        h[i][o] = fmaxf(s, 0.f);
    }
    __syncthreads();

    // LUT rows 1..5 : ne = h @ Wf^T + bf  [5,16]
    if (t < N_NODES * EMB) {
        int i = t / EMB, e = t % EMB;
        float s = bf[e];
        #pragma unroll
        for (int j = 0; j < HID; j++) s += h[i][j] * Wf[e * HID + j];
        g_lut[(i + 1) * EMB + e] = s;
    }
    // LUT row 0 : emb_table row 0 (gs==0 path)
    if (t < EMB) g_lut[t] = emb[t];
}

// ---------------------------------------------------------------------------
// Kernel 2: HBM-streaming scatter. 4 threads per cell, one float4 each.
// Out layout: [cell][16 floats] -> a warp covers 8 consecutive cells
// = 512B of fully-coalesced STG.128 stores. Grid-stride for robustness.
// ---------------------------------------------------------------------------
__global__ void scatter_lut(const int* __restrict__ gs,
                            float4* __restrict__ out,
                            long long nquads)
{
    const long long stride = (long long)gridDim.x * blockDim.x;
    for (long long idx = (long long)blockIdx.x * blockDim.x + threadIdx.x;
         idx < nquads; idx += stride)
    {
        const int cell = (int)(idx >> 2);
        const int q    = (int)(idx & 3);

        int c = __ldg(gs + cell);
        c = min(max(c, 0), 5);   // safety clamp; reference clips to valid rows

        const float4* lut4 = reinterpret_cast<const float4*>(g_lut);
        out[idx] = __ldg(lut4 + c * 4 + q);
    }
}

// ---------------------------------------------------------------------------
extern "C" void kernel_launch(void* const* d_in, const int* in_sizes, int n_in,
                              void* d_out, int out_size)
{
    const int*   gs  = (const int*)d_in[0];    // game_state [256,128,128]
    const float* emb = (const float*)d_in[1];  // [5,16]
    const float* A   = (const float*)d_in[2];  // [5,5]
    const float* W0  = (const float*)d_in[3];  // [32,16]
    const float* W1  = (const float*)d_in[4];  // [32,32]
    const float* W2  = (const float*)d_in[5];  // [32,32]
    const float* Wf  = (const float*)d_in[6];  // [16,32]
    const float* bf  = (const float*)d_in[7];  // [16]
    float4* out = (float4*)d_out;

    const int ncells = in_sizes[0];            // 4,194,304

    gcn_build_lut<<<1, 192>>>(emb, A, W0, W1, W2, Wf, bf);

    const long long nquads = (long long)ncells * 4;   // 16,777,216 float4 stores
    const int threads = 256;
    long long want = (nquads + threads - 1) / threads;
    int blocks = (want > 1048576LL) ? 1048576 : (int)want;
    scatter_lut<<<blocks, threads>>>(gs, out, nquads);
}

// round 5
// speedup vs baseline: 1.3677x; 1.3677x over previous
#include <cuda_runtime.h>
#include <cuda_bf16.h>

#define N_NODES 5
#define EMB 16
#define HID 32

// LUT[c][e] : value to write for a cell whose game_state char == c, c in 0..5.
// c == 0      -> emb_table[0][e]   (gse fallback)
// c in 1..5   -> node_emb[c-1][e]  (GCN output rows)
__device__ float g_lut[6 * EMB];

// ---------------------------------------------------------------------------
// Kernel 1: tiny GCN on 5 nodes -> fill g_lut. One block, 192 threads.
// All weights are prefetched into smem in parallel first, so the 6 dependent
// stages pay only smem latency, not 6 serial global-load latencies.
// ---------------------------------------------------------------------------
__global__ void gcn_build_lut(const float* __restrict__ emb,   // [5,16]
                              const float* __restrict__ A,     // [5,5]
                              const float* __restrict__ W0,    // [32,16]
                              const float* __restrict__ W1,    // [32,32]
                              const float* __restrict__ W2,    // [32,32]
                              const float* __restrict__ Wf,    // [16,32]
                              const float* __restrict__ bf)    // [16]
{
    __shared__ float sE[N_NODES * EMB];     // 80
    __shared__ float sA[N_NODES * N_NODES]; // 25
    __shared__ float sW0[HID * EMB];        // 512
    __shared__ float sW1[HID * HID];        // 1024
    __shared__ float sW2[HID * HID];        // 1024
    __shared__ float sWf[EMB * HID];        // 512
    __shared__ float sbf[EMB];              // 16
    __shared__ float x0[N_NODES][EMB];
    __shared__ float h[N_NODES][HID];
    __shared__ float y[N_NODES][HID];

    const int t = threadIdx.x;
    const int NT = blockDim.x;

    // parallel prefetch of everything (independent loads, one latency)
    for (int i = t; i < N_NODES * EMB; i += NT) sE[i] = emb[i];
    for (int i = t; i < N_NODES * N_NODES; i += NT) sA[i] = A[i];
    for (int i = t; i < HID * EMB; i += NT) sW0[i] = W0[i];
    for (int i = t; i < HID * HID; i += NT) sW1[i] = W1[i];
    for (int i = t; i < HID * HID; i += NT) sW2[i] = W2[i];
    for (int i = t; i < EMB * HID; i += NT) sWf[i] = Wf[i];
    for (int i = t; i < EMB; i += NT) sbf[i] = bf[i];
    __syncthreads();

    // x0 = A @ emb_table  [5,16]
    if (t < N_NODES * EMB) {
        int i = t / EMB, j = t % EMB;
        float s = 0.f;
        #pragma unroll
        for (int k = 0; k < N_NODES; k++) s += sA[i * N_NODES + k] * sE[k * EMB + j];
        x0[i][j] = s;
    }
    __syncthreads();

    // h = relu(x0 @ W0^T)
    if (t < N_NODES * HID) {
        int i = t / HID, o = t % HID;
        float s = 0.f;
        #pragma unroll
        for (int j = 0; j < EMB; j++) s += x0[i][j] * sW0[o * EMB + j];
        h[i][o] = fmaxf(s, 0.f);
    }
    __syncthreads();

    // round 1: y = A@h ; h = relu(y @ W1^T)
    if (t < N_NODES * HID) {
        int i = t / HID, o = t % HID;
        float s = 0.f;
        #pragma unroll
        for (int k = 0; k < N_NODES; k++) s += sA[i * N_NODES + k] * h[k][o];
        y[i][o] = s;
    }
    __syncthreads();
    if (t < N_NODES * HID) {
        int i = t / HID, o = t % HID;
        float s = 0.f;
        #pragma unroll
        for (int j = 0; j < HID; j++) s += y[i][j] * sW1[o * HID + j];
        h[i][o] = fmaxf(s, 0.f);
    }
    __syncthreads();

    // round 2: y = A@h ; h = relu(y @ W2^T)
    if (t < N_NODES * HID) {
        int i = t / HID, o = t % HID;
        float s = 0.f;
        #pragma unroll
        for (int k = 0; k < N_NODES; k++) s += sA[i * N_NODES + k] * h[k][o];
        y[i][o] = s;
    }
    __syncthreads();
    if (t < N_NODES * HID) {
        int i = t / HID, o = t % HID;
        float s = 0.f;
        #pragma unroll
        for (int j = 0; j < HID; j++) s += y[i][j] * sW2[o * HID + j];
        h[i][o] = fmaxf(s, 0.f);
    }
    __syncthreads();

    // LUT rows 1..5 : h @ Wf^T + bf  [5,16]
    if (t < N_NODES * EMB) {
        int i = t / EMB, e = t % EMB;
        float s = sbf[e];
        #pragma unroll
        for (int j = 0; j < HID; j++) s += h[i][j] * sWf[e * HID + j];
        g_lut[(i + 1) * EMB + e] = s;
    }
    // LUT row 0 : emb_table row 0 (gs==0 path)
    if (t < EMB) g_lut[t] = sE[t];
}

// ---------------------------------------------------------------------------
// Kernel 2: HBM-streaming scatter.
// Block tile = 1024 quads (16KB out). Thread t handles quads
// {t, t+256, t+512, t+768}: every STG.128 is a fully-coalesced 512B/warp
// stream, and per-quad overhead is LDG + IMAD + LDG.128 + STG.128 with
// immediate offsets (setup amortized 4x, gs loads give MLP=4).
// ---------------------------------------------------------------------------
#define TPB 256
#define QPT 4
#define TILE (TPB * QPT)   // 1024 quads per block

__global__ void __launch_bounds__(TPB) scatter_lut(const int* __restrict__ gs,
                                                   float4* __restrict__ out,
                                                   int nquads)
{
    const int tid  = threadIdx.x;
    const int base = blockIdx.x * TILE + tid;          // quad index, iter 0
    const int q    = tid & 3;                          // lane-within-cell (TILE%4==0)

    const float4* __restrict__ lutq = reinterpret_cast<const float4*>(g_lut) + q;
    const int*    __restrict__ g    = gs + (base >> 2);
    float4*       __restrict__ o    = out + base;

    if (base + (QPT - 1) * TPB < nquads) {
        // fast path: whole strip in range (always taken for the bench shape)
        int c0 = __ldg(g + 0 * (TPB >> 2));
        int c1 = __ldg(g + 1 * (TPB >> 2));
        int c2 = __ldg(g + 2 * (TPB >> 2));
        int c3 = __ldg(g + 3 * (TPB >> 2));
        float4 v0 = __ldg(lutq + c0 * 4);
        float4 v1 = __ldg(lutq + c1 * 4);
        float4 v2 = __ldg(lutq + c2 * 4);
        float4 v3 = __ldg(lutq + c3 * 4);
        o[0 * TPB] = v0;
        o[1 * TPB] = v1;
        o[2 * TPB] = v2;
        o[3 * TPB] = v3;
    } else {
        #pragma unroll
        for (int u = 0; u < QPT; u++) {
            int idx = base + u * TPB;
            if (idx < nquads) {
                int c = __ldg(g + u * (TPB >> 2));
                o[u * TPB] = __ldg(lutq + c * 4);
            }
        }
    }
}

// ---------------------------------------------------------------------------
extern "C" void kernel_launch(void* const* d_in, const int* in_sizes, int n_in,
                              void* d_out, int out_size)
{
    const int*   gs  = (const int*)d_in[0];    // game_state [256,128,128]
    const float* emb = (const float*)d_in[1];  // [5,16]
    const float* A   = (const float*)d_in[2];  // [5,5]
    const float* W0  = (const float*)d_in[3];  // [32,16]
    const float* W1  = (const float*)d_in[4];  // [32,32]
    const float* W2  = (const float*)d_in[5];  // [32,32]
    const float* Wf  = (const float*)d_in[6];  // [16,32]
    const float* bf  = (const float*)d_in[7];  // [16]
    float4* out = (float4*)d_out;

    const int ncells = in_sizes[0];            // 4,194,304
    const int nquads = ncells * 4;             // 16,777,216 float4 stores

    gcn_build_lut<<<1, 192>>>(emb, A, W0, W1, W2, Wf, bf);

    const int blocks = (nquads + TILE - 1) / TILE;   // 16384
    scatter_lut<<<blocks, TPB>>>(gs, out, nquads);
}

// round 6
// speedup vs baseline: 1.6732x; 1.2234x over previous
#include <cuda_runtime.h>
#include <cuda_bf16.h>

#define N_NODES 5
#define EMB 16
#define HID 32

// LUT[c][e] : value for a cell whose game_state char == c, c in 0..5.
// c == 0    -> emb_table[0][e]   (gse fallback)
// c in 1..5 -> node_emb[c-1][e]  (GCN output rows)
__device__ float g_lut[6 * EMB];

// ---------------------------------------------------------------------------
// Kernel 1: tiny GCN on 5 nodes -> fill g_lut. One block, 192 threads.
// Weights prefetched to smem in parallel (one global-load latency total).
// ---------------------------------------------------------------------------
__global__ void gcn_build_lut(const float* __restrict__ emb,   // [5,16]
                              const float* __restrict__ A,     // [5,5]
                              const float* __restrict__ W0,    // [32,16]
                              const float* __restrict__ W1,    // [32,32]
                              const float* __restrict__ W2,    // [32,32]
                              const float* __restrict__ Wf,    // [16,32]
                              const float* __restrict__ bf)    // [16]
{
    __shared__ float sE[N_NODES * EMB];
    __shared__ float sA[N_NODES * N_NODES];
    __shared__ float sW0[HID * EMB];
    __shared__ float sW1[HID * HID];
    __shared__ float sW2[HID * HID];
    __shared__ float sWf[EMB * HID];
    __shared__ float sbf[EMB];
    __shared__ float x0[N_NODES][EMB];
    __shared__ float h[N_NODES][HID];
    __shared__ float y[N_NODES][HID];

    const int t = threadIdx.x;
    const int NT = blockDim.x;

    for (int i = t; i < N_NODES * EMB; i += NT) sE[i] = emb[i];
    for (int i = t; i < N_NODES * N_NODES; i += NT) sA[i] = A[i];
    for (int i = t; i < HID * EMB; i += NT) sW0[i] = W0[i];
    for (int i = t; i < HID * HID; i += NT) sW1[i] = W1[i];
    for (int i = t; i < HID * HID; i += NT) sW2[i] = W2[i];
    for (int i = t; i < EMB * HID; i += NT) sWf[i] = Wf[i];
    for (int i = t; i < EMB; i += NT) sbf[i] = bf[i];
    __syncthreads();

    if (t < N_NODES * EMB) {
        int i = t / EMB, j = t % EMB;
        float s = 0.f;
        #pragma unroll
        for (int k = 0; k < N_NODES; k++) s += sA[i * N_NODES + k] * sE[k * EMB + j];
        x0[i][j] = s;
    }
    __syncthreads();

    if (t < N_NODES * HID) {
        int i = t / HID, o = t % HID;
        float s = 0.f;
        #pragma unroll
        for (int j = 0; j < EMB; j++) s += x0[i][j] * sW0[o * EMB + j];
        h[i][o] = fmaxf(s, 0.f);
    }
    __syncthreads();

    if (t < N_NODES * HID) {
        int i = t / HID, o = t % HID;
        float s = 0.f;
        #pragma unroll
        for (int k = 0; k < N_NODES; k++) s += sA[i * N_NODES + k] * h[k][o];
        y[i][o] = s;
    }
    __syncthreads();
    if (t < N_NODES * HID) {
        int i = t / HID, o = t % HID;
        float s = 0.f;
        #pragma unroll
        for (int j = 0; j < HID; j++) s += y[i][j] * sW1[o * HID + j];
        h[i][o] = fmaxf(s, 0.f);
    }
    __syncthreads();

    if (t < N_NODES * HID) {
        int i = t / HID, o = t % HID;
        float s = 0.f;
        #pragma unroll
        for (int k = 0; k < N_NODES; k++) s += sA[i * N_NODES + k] * h[k][o];
        y[i][o] = s;
    }
    __syncthreads();
    if (t < N_NODES * HID) {
        int i = t / HID, o = t % HID;
        float s = 0.f;
        #pragma unroll
        for (int j = 0; j < HID; j++) s += y[i][j] * sW2[o * HID + j];
        h[i][o] = fmaxf(s, 0.f);
    }
    __syncthreads();

    if (t < N_NODES * EMB) {
        int i = t / EMB, e = t % EMB;
        float s = sbf[e];
        #pragma unroll
        for (int j = 0; j < HID; j++) s += h[i][j] * sWf[e * HID + j];
        g_lut[(i + 1) * EMB + e] = s;
    }
    if (t < EMB) g_lut[t] = sE[t];
}

// ---------------------------------------------------------------------------
// Kernel 2: HBM-streaming scatter.
// Block tile = 2048 quads (32KB out). Thread t handles quads {t + u*256}.
// LUT lives in smem (LDS.128, separate port from the L1 store path); the
// 256MB output goes out via streaming __stcs stores (never re-read).
// ---------------------------------------------------------------------------
#define TPB 256
#define QPT 8
#define TILE (TPB * QPT)   // 2048 quads per block

__global__ void __launch_bounds__(TPB) scatter_lut(const int* __restrict__ gs,
                                                   float4* __restrict__ out,
                                                   int nquads)
{
    __shared__ float4 slut[6 * 4];   // 6 rows x 4 quads = 96 floats

    const int tid = threadIdx.x;
    if (tid < 24) {
        slut[tid] = reinterpret_cast<const float4*>(g_lut)[tid];
    }
    __syncthreads();

    const int base = blockIdx.x * TILE + tid;   // quad index, iter 0
    const int q    = tid & 3;                   // lane-within-cell (TILE%4==0)

    const float4* __restrict__ lutq = slut + q;
    const int*    __restrict__ g    = gs + (base >> 2);
    float4*       __restrict__ o    = out + base;

    if (base + (QPT - 1) * TPB < nquads) {
        // fast path (always taken for the bench shape): 8 independent strips
        int c[QPT];
        #pragma unroll
        for (int u = 0; u < QPT; u++) c[u] = __ldg(g + u * (TPB >> 2));
        #pragma unroll
        for (int u = 0; u < QPT; u++) {
            float4 v = lutq[c[u] * 4];
            __stcs(o + u * TPB, v);
        }
    } else {
        #pragma unroll
        for (int u = 0; u < QPT; u++) {
            int idx = base + u * TPB;
            if (idx < nquads) {
                int c = __ldg(g + u * (TPB >> 2));
                __stcs(o + u * TPB, lutq[c * 4]);
            }
        }
    }
}

// ---------------------------------------------------------------------------
extern "C" void kernel_launch(void* const* d_in, const int* in_sizes, int n_in,
                              void* d_out, int out_size)
{
    const int*   gs  = (const int*)d_in[0];    // game_state [256,128,128]
    const float* emb = (const float*)d_in[1];  // [5,16]
    const float* A   = (const float*)d_in[2];  // [5,5]
    const float* W0  = (const float*)d_in[3];  // [32,16]
    const float* W1  = (const float*)d_in[4];  // [32,32]
    const float* W2  = (const float*)d_in[5];  // [32,32]
    const float* Wf  = (const float*)d_in[6];  // [16,32]
    const float* bf  = (const float*)d_in[7];  // [16]
    float4* out = (float4*)d_out;

    const int ncells = in_sizes[0];            // 4,194,304
    const int nquads = ncells * 4;             // 16,777,216 float4 stores

    gcn_build_lut<<<1, 192>>>(emb, A, W0, W1, W2, Wf, bf);

    const int blocks = (nquads + TILE - 1) / TILE;   // 8192
    scatter_lut<<<blocks, TPB>>>(gs, out, nquads);
}